// round 1
// baseline (speedup 1.0000x reference)
#include <cuda_runtime.h>
#include <math.h>

// Problem dims
#define SLEN 1024
#define BSZ  32
#define NH   16
#define DH   64
#define INDIM 1024            // NH*DH
#define MROWS (SLEN*BSZ)      // 32768

// Scratch (device globals; no allocation allowed)
__device__ float g_ys[(size_t)MROWS * INDIM];   // scan output (T*B, 1024)
__device__ float g_mu[MROWS];
__device__ float g_rstd[MROWS];

// ---------------------------------------------------------------------------
// 64-thread (2-warp) block reduction, N values at once, broadcast to all.
// red must hold >= 16 floats.
// ---------------------------------------------------------------------------
template<int N, bool IS_MAX>
__device__ __forceinline__ void reduce64(float* v, float* red, int warp, int lane) {
  #pragma unroll
  for (int off = 16; off > 0; off >>= 1) {
    #pragma unroll
    for (int i = 0; i < N; i++) {
      float o = __shfl_xor_sync(0xffffffffu, v[i], off);
      v[i] = IS_MAX ? fmaxf(v[i], o) : (v[i] + o);
    }
  }
  if (lane == 0) {
    #pragma unroll
    for (int i = 0; i < N; i++) red[warp * 8 + i] = v[i];
  }
  __syncthreads();
  #pragma unroll
  for (int i = 0; i < N; i++)
    v[i] = IS_MAX ? fmaxf(red[i], red[8 + i]) : (red[i] + red[8 + i]);
  __syncthreads();
}

// ---------------------------------------------------------------------------
// SRWM sequential scan. One 64-thread CTA per (batch, head) unit; thread o
// owns row o of Wy/Wq/Wk (register-resident) and row o of wb.
// ---------------------------------------------------------------------------
__global__ void __launch_bounds__(64, 4) srwm_scan(
    const float* __restrict__ hin,   // (T, B, 1024)
    const float* __restrict__ Wy0,   // (1, 16, 64, 64)
    const float* __restrict__ Wq0,
    const float* __restrict__ Wk0,
    const float* __restrict__ wb0)   // (1, 16, 64, 4)
{
  const int unit = blockIdx.x;          // 0..511
  const int b    = unit >> 4;
  const int hd   = unit & 15;
  const int tid  = threadIdx.x;         // output row o
  const int lane = tid & 31;
  const int warp = tid >> 5;

  __shared__ float x_s[DH];
  __shared__ float q_s[DH];
  __shared__ float k_s[DH];
  __shared__ float red[16];

  float wy[DH], wq[DH], wk[DH], wbr[4];

  // Load initial weights (same for all b, indexed by head)
  {
    const float4* py = (const float4*)(Wy0 + (size_t)(hd * DH + tid) * DH);
    const float4* pq = (const float4*)(Wq0 + (size_t)(hd * DH + tid) * DH);
    const float4* pk = (const float4*)(Wk0 + (size_t)(hd * DH + tid) * DH);
    #pragma unroll
    for (int c = 0; c < DH / 4; c++) {
      float4 vy = py[c]; wy[4*c] = vy.x; wy[4*c+1] = vy.y; wy[4*c+2] = vy.z; wy[4*c+3] = vy.w;
      float4 vq = pq[c]; wq[4*c] = vq.x; wq[4*c+1] = vq.y; wq[4*c+2] = vq.z; wq[4*c+3] = vq.w;
      float4 vk = pk[c]; wk[4*c] = vk.x; wk[4*c+1] = vk.y; wk[4*c+2] = vk.z; wk[4*c+3] = vk.w;
    }
    float4 vb = *(const float4*)(wb0 + (size_t)(hd * DH + tid) * 4);
    wbr[0] = vb.x; wbr[1] = vb.y; wbr[2] = vb.z; wbr[3] = vb.w;
  }

  const float* xin  = hin + (size_t)b * INDIM + hd * DH;     // + t*B*1024
  float*       yout = g_ys + (size_t)(b * NH + hd) * DH;     // + t*B*H*D

  for (int t = 0; t < SLEN; t++) {
    // broadcast x_t
    x_s[tid] = xin[(size_t)t * (BSZ * INDIM) + tid];
    __syncthreads();

    // Pass 1: y = Wy x, zq = Wq x, zk = Wk x  (old weights)
    float sy = 0.f, sq = 0.f, sk = 0.f;
    #pragma unroll
    for (int d = 0; d < DH; d++) {
      float xd = x_s[d];
      sy = fmaf(wy[d], xd, sy);
      sq = fmaf(wq[d], xd, sq);
      sk = fmaf(wk[d], xd, sk);
    }
    float xo = x_s[tid];

    // max reductions for the three softmaxes
    float r3[3] = {sq, sk, sy};
    reduce64<3, true>(r3, red, warp, lane);
    float eq = expf(sq - r3[0]);
    float ek = expf(sk - r3[1]);
    float ey = expf(sy - r3[2]);

    // sum reductions: exp sums + beta logits (wb^T x)
    float r7[7] = {eq, ek, ey, wbr[0]*xo, wbr[1]*xo, wbr[2]*xo, wbr[3]*xo};
    reduce64<7, false>(r7, red, warp, lane);

    float qv   = eq / r7[0];
    float kv   = ek / r7[1];
    float outv = ey / r7[2];
    float beta0 = 1.f / (1.f + expf(-r7[3]));
    float beta1 = 1.f / (1.f + expf(-r7[4]));
    float beta2 = 1.f / (1.f + expf(-r7[5]));
    float beta3 = 1.f / (1.f + expf(-r7[6]));

    q_s[tid] = qv;
    k_s[tid] = kv;
    __syncthreads();

    // Pass 2: W q and W k for all three matrices (old weights)
    float syq = 0.f, syk = 0.f, sqq = 0.f, sqk = 0.f, skq = 0.f, skk = 0.f;
    #pragma unroll
    for (int d = 0; d < DH; d++) {
      float qd = q_s[d], kd = k_s[d];
      syq = fmaf(wy[d], qd, syq); syk = fmaf(wy[d], kd, syk);
      sqq = fmaf(wq[d], qd, sqq); sqk = fmaf(wq[d], kd, sqk);
      skq = fmaf(wk[d], qd, skq); skk = fmaf(wk[d], kd, skk);
    }

    // bq = wb^T q, bk = wb^T k
    float r8[8] = {wbr[0]*qv, wbr[1]*qv, wbr[2]*qv, wbr[3]*qv,
                   wbr[0]*kv, wbr[1]*kv, wbr[2]*kv, wbr[3]*kv};
    reduce64<8, false>(r8, red, warp, lane);

    // Rank-1 delta-rule updates
    float cy = beta0 * (syq - syk);
    float cq = beta1 * (sqq - sqk);
    float ck = beta2 * (skq - skk);
    #pragma unroll
    for (int d = 0; d < DH; d++) {
      float kd = k_s[d];
      wy[d] = fmaf(cy, kd, wy[d]);
      wq[d] = fmaf(cq, kd, wq[d]);
      wk[d] = fmaf(ck, kd, wk[d]);
    }
    float bko = beta3 * kv;
    #pragma unroll
    for (int j = 0; j < 4; j++)
      wbr[j] = fmaf(bko, r8[j] - r8[4 + j], wbr[j]);

    // out_t = softmax(y)
    yout[(size_t)t * (BSZ * NH * DH) + tid] = outv;
  }
}

// ---------------------------------------------------------------------------
// LayerNorm row statistics for h (32768 rows of 1024)
// ---------------------------------------------------------------------------
__global__ void __launch_bounds__(256) ln_stats_kernel(const float* __restrict__ hin)
{
  const int row  = blockIdx.x;
  const int tid  = threadIdx.x;
  const int lane = tid & 31;
  const int warp = tid >> 5;

  float4 v = *(const float4*)(hin + (size_t)row * INDIM + tid * 4);
  float s  = v.x + v.y + v.z + v.w;
  float s2 = v.x * v.x + v.y * v.y + v.z * v.z + v.w * v.w;

  #pragma unroll
  for (int off = 16; off > 0; off >>= 1) {
    s  += __shfl_xor_sync(0xffffffffu, s, off);
    s2 += __shfl_xor_sync(0xffffffffu, s2, off);
  }
  __shared__ float sa[8], sb[8];
  if (lane == 0) { sa[warp] = s; sb[warp] = s2; }
  __syncthreads();
  if (tid == 0) {
    float S = 0.f, S2 = 0.f;
    #pragma unroll
    for (int i = 0; i < 8; i++) { S += sa[i]; S2 += sb[i]; }
    float m   = S * (1.f / INDIM);
    float var = S2 * (1.f / INDIM) - m * m;
    g_mu[row]   = m;
    g_rstd[row] = rsqrtf(var + 1e-5f);
  }
}

// ---------------------------------------------------------------------------
// out = ys @ out_w^T + LN(h)*g + b
// A = g_ys (M x K, row-major), B = out_w (N x K, row-major). 128x128x16 tiles.
// ---------------------------------------------------------------------------
#define BM 128
#define BN 128
#define BK 16

__global__ void __launch_bounds__(256) gemm_ln_kernel(
    const float* __restrict__ Bw,     // out_w (1024,1024)
    const float* __restrict__ hin,    // residual + LN source
    const float* __restrict__ gvec,   // ln_g
    const float* __restrict__ bvec,   // ln_b
    float* __restrict__ out)
{
  __shared__ float As[BK][BM + 4];
  __shared__ float Bs[BK][BN + 4];

  const int m0  = blockIdx.y * BM;
  const int n0  = blockIdx.x * BN;
  const int tid = threadIdx.x;
  const int tx  = tid & 15;   // 0..15 -> n groups of 8
  const int ty  = tid >> 4;   // 0..15 -> m groups of 8

  float acc[8][8];
  #pragma unroll
  for (int i = 0; i < 8; i++)
    #pragma unroll
    for (int j = 0; j < 8; j++) acc[i][j] = 0.f;

  const float* A = g_ys;

  for (int k0 = 0; k0 < INDIM; k0 += BK) {
    #pragma unroll
    for (int l = 0; l < 2; l++) {
      int idx = tid + l * 256;        // 0..511
      int m   = idx >> 2;             // 0..127
      int kq  = idx & 3;              // 0..3 (group of 4 k)
      float4 va = *(const float4*)(A  + (size_t)(m0 + m) * INDIM + k0 + kq * 4);
      As[kq*4+0][m] = va.x; As[kq*4+1][m] = va.y;
      As[kq*4+2][m] = va.z; As[kq*4+3][m] = va.w;
      float4 vb = *(const float4*)(Bw + (size_t)(n0 + m) * INDIM + k0 + kq * 4);
      Bs[kq*4+0][m] = vb.x; Bs[kq*4+1][m] = vb.y;
      Bs[kq*4+2][m] = vb.z; Bs[kq*4+3][m] = vb.w;
    }
    __syncthreads();

    #pragma unroll
    for (int k = 0; k < BK; k++) {
      float a[8], bb[8];
      #pragma unroll
      for (int i = 0; i < 8; i++) a[i]  = As[k][ty * 8 + i];
      #pragma unroll
      for (int j = 0; j < 8; j++) bb[j] = Bs[k][tx * 8 + j];
      #pragma unroll
      for (int i = 0; i < 8; i++)
        #pragma unroll
        for (int j = 0; j < 8; j++)
          acc[i][j] = fmaf(a[i], bb[j], acc[i][j]);
    }
    __syncthreads();
  }

  // Epilogue: add LN(h) residual
  #pragma unroll
  for (int i = 0; i < 8; i++) {
    int m = m0 + ty * 8 + i;
    float muv = g_mu[m];
    float rs  = g_rstd[m];
    #pragma unroll
    for (int j = 0; j < 8; j += 4) {
      int n = n0 + tx * 8 + j;
      float4 hv = *(const float4*)(hin + (size_t)m * INDIM + n);
      float4 gv = *(const float4*)(gvec + n);
      float4 bv = *(const float4*)(bvec + n);
      float4 o;
      o.x = acc[i][j+0] + (hv.x - muv) * rs * gv.x + bv.x;
      o.y = acc[i][j+1] + (hv.y - muv) * rs * gv.y + bv.y;
      o.z = acc[i][j+2] + (hv.z - muv) * rs * gv.z + bv.z;
      o.w = acc[i][j+3] + (hv.w - muv) * rs * gv.w + bv.w;
      *(float4*)(out + (size_t)m * INDIM + n) = o;
    }
  }
}

// ---------------------------------------------------------------------------
extern "C" void kernel_launch(void* const* d_in, const int* in_sizes, int n_in,
                              void* d_out, int out_size)
{
  const float* h_in = (const float*)d_in[0];
  const float* W_y  = (const float*)d_in[1];
  const float* W_q  = (const float*)d_in[2];
  const float* W_k  = (const float*)d_in[3];
  const float* w_b  = (const float*)d_in[4];
  const float* outw = (const float*)d_in[5];
  const float* ln_g = (const float*)d_in[6];
  const float* ln_b = (const float*)d_in[7];
  float* out = (float*)d_out;

  // LN stats (independent of scan)
  ln_stats_kernel<<<MROWS, 256>>>(h_in);

  // Sequential SRWM scan: 512 units, 64 threads each
  srwm_scan<<<BSZ * NH, 64>>>(h_in, W_y, W_q, W_k, w_b);

  // Output GEMM + LN residual
  dim3 grid(INDIM / BN, MROWS / BM);
  gemm_ln_kernel<<<grid, 256>>>(outw, h_in, ln_g, ln_b, out);
}

// round 4
// speedup vs baseline: 1.3989x; 1.3989x over previous
#include <cuda_runtime.h>
#include <cuda_bf16.h>
#include <math.h>

// Problem dims
#define SLEN 1024
#define BSZ  32
#define NH   16
#define DH   64
#define INDIM 1024            // NH*DH
#define MROWS (SLEN*BSZ)      // 32768

typedef unsigned long long u64;

// Scratch (device globals; no allocation allowed)
__device__ __nv_bfloat16 g_ys_bf[(size_t)MROWS * INDIM];   // scan output, bf16
__device__ __nv_bfloat16 g_wb16[(size_t)INDIM * INDIM];    // out_w in bf16
__device__ float g_mu[MROWS];
__device__ float g_rstd[MROWS];

// ---------------------------------------------------------------------------
// packed f32x2 helpers
// ---------------------------------------------------------------------------
__device__ __forceinline__ u64 pack2(float lo, float hi) {
  u64 r; asm("mov.b64 %0, {%1, %2};" : "=l"(r) : "f"(lo), "f"(hi)); return r;
}
__device__ __forceinline__ void unpack2(u64 v, float& lo, float& hi) {
  asm("mov.b64 {%0, %1}, %2;" : "=f"(lo), "=f"(hi) : "l"(v));
}
__device__ __forceinline__ u64 fma2(u64 a, u64 b, u64 c) {
  u64 d; asm("fma.rn.f32x2 %0, %1, %2, %3;" : "=l"(d) : "l"(a), "l"(b), "l"(c));
  return d;
}

// ---------------------------------------------------------------------------
// 64-thread (2-warp) block reduction, N values at once, broadcast to all.
// ---------------------------------------------------------------------------
template<int N, bool IS_MAX>
__device__ __forceinline__ void reduce64(float* v, float* red, int warp, int lane) {
  #pragma unroll
  for (int off = 16; off > 0; off >>= 1) {
    #pragma unroll
    for (int i = 0; i < N; i++) {
      float o = __shfl_xor_sync(0xffffffffu, v[i], off);
      v[i] = IS_MAX ? fmaxf(v[i], o) : (v[i] + o);
    }
  }
  if (lane == 0) {
    #pragma unroll
    for (int i = 0; i < N; i++) red[warp * 8 + i] = v[i];
  }
  __syncthreads();
  #pragma unroll
  for (int i = 0; i < N; i++)
    v[i] = IS_MAX ? fmaxf(red[i], red[8 + i]) : (red[i] + red[8 + i]);
  __syncthreads();
}

// ---------------------------------------------------------------------------
// SRWM sequential scan. One 64-thread CTA per (batch, head) unit; thread o
// owns row o of Wy/Wq/Wk as 32 packed f32x2 each.
// ---------------------------------------------------------------------------
__global__ void __launch_bounds__(64, 4) srwm_scan(
    const float* __restrict__ hin,   // (T, B, 1024)
    const float* __restrict__ Wy0,   // (1, 16, 64, 64)
    const float* __restrict__ Wq0,
    const float* __restrict__ Wk0,
    const float* __restrict__ wb0)   // (1, 16, 64, 4)
{
  const int unit = blockIdx.x;          // 0..511
  const int b    = unit >> 4;
  const int hd   = unit & 15;
  const int tid  = threadIdx.x;         // output row o
  const int lane = tid & 31;
  const int warp = tid >> 5;

  __shared__ __align__(8) float x_s[DH];
  __shared__ __align__(8) float q_s[DH];
  __shared__ __align__(8) float k_s[DH];
  __shared__ float red[16];

  u64 wy2[DH/2], wq2[DH/2], wk2[DH/2];
  float wbr[4];

  // Load initial weights (indexed by head only)
  {
    const float4* py = (const float4*)(Wy0 + (size_t)(hd * DH + tid) * DH);
    const float4* pq = (const float4*)(Wq0 + (size_t)(hd * DH + tid) * DH);
    const float4* pk = (const float4*)(Wk0 + (size_t)(hd * DH + tid) * DH);
    #pragma unroll
    for (int c = 0; c < DH / 4; c++) {
      float4 vy = py[c];
      wy2[2*c]   = pack2(vy.x, vy.y);
      wy2[2*c+1] = pack2(vy.z, vy.w);
      float4 vq = pq[c];
      wq2[2*c]   = pack2(vq.x, vq.y);
      wq2[2*c+1] = pack2(vq.z, vq.w);
      float4 vk = pk[c];
      wk2[2*c]   = pack2(vk.x, vk.y);
      wk2[2*c+1] = pack2(vk.z, vk.w);
    }
    float4 vb = *(const float4*)(wb0 + (size_t)(hd * DH + tid) * 4);
    wbr[0] = vb.x; wbr[1] = vb.y; wbr[2] = vb.z; wbr[3] = vb.w;
  }

  const float* xin = hin + (size_t)b * INDIM + hd * DH;
  __nv_bfloat16* yout = g_ys_bf + (size_t)b * INDIM + hd * DH;

  const u64* x2 = (const u64*)x_s;
  const u64* q2 = (const u64*)q_s;
  const u64* k2 = (const u64*)k_s;

  for (int t = 0; t < SLEN; t++) {
    x_s[tid] = xin[(size_t)t * (BSZ * INDIM) + tid];
    __syncthreads();

    // Pass 1: y = Wy x, zq = Wq x, zk = Wk x  (packed)
    u64 aY = 0, aQ = 0, aK = 0;
    #pragma unroll
    for (int d = 0; d < DH/2; d++) {
      u64 xd = x2[d];
      aY = fma2(wy2[d], xd, aY);
      aQ = fma2(wq2[d], xd, aQ);
      aK = fma2(wk2[d], xd, aK);
    }
    float yl, yh, ql, qh, kl, kh;
    unpack2(aY, yl, yh); unpack2(aQ, ql, qh); unpack2(aK, kl, kh);
    float sy = yl + yh, sq = ql + qh, sk = kl + kh;
    float xo = x_s[tid];

    // max reductions for the three softmaxes
    float r3[3] = {sq, sk, sy};
    reduce64<3, true>(r3, red, warp, lane);
    float eq = __expf(sq - r3[0]);
    float ek = __expf(sk - r3[1]);
    float ey = __expf(sy - r3[2]);

    // sum reductions: exp sums + beta logits (wb^T x)
    float r7[7] = {eq, ek, ey, wbr[0]*xo, wbr[1]*xo, wbr[2]*xo, wbr[3]*xo};
    reduce64<7, false>(r7, red, warp, lane);

    float qv   = eq / r7[0];
    float kv   = ek / r7[1];
    float outv = ey / r7[2];
    float beta0 = 1.f / (1.f + __expf(-r7[3]));
    float beta1 = 1.f / (1.f + __expf(-r7[4]));
    float beta2 = 1.f / (1.f + __expf(-r7[5]));
    float beta3 = 1.f / (1.f + __expf(-r7[6]));

    q_s[tid] = qv;
    k_s[tid] = kv;
    __syncthreads();

    // Pass 2: W q and W k for all three matrices (packed)
    u64 aYQ = 0, aYK = 0, aQQ = 0, aQK = 0, aKQ = 0, aKK = 0;
    #pragma unroll
    for (int d = 0; d < DH/2; d++) {
      u64 qd = q2[d], kd = k2[d];
      aYQ = fma2(wy2[d], qd, aYQ); aYK = fma2(wy2[d], kd, aYK);
      aQQ = fma2(wq2[d], qd, aQQ); aQK = fma2(wq2[d], kd, aQK);
      aKQ = fma2(wk2[d], qd, aKQ); aKK = fma2(wk2[d], kd, aKK);
    }
    float t0, t1;
    unpack2(aYQ, t0, t1); float syq = t0 + t1;
    unpack2(aYK, t0, t1); float syk = t0 + t1;
    unpack2(aQQ, t0, t1); float sqq = t0 + t1;
    unpack2(aQK, t0, t1); float sqk = t0 + t1;
    unpack2(aKQ, t0, t1); float skq = t0 + t1;
    unpack2(aKK, t0, t1); float skk = t0 + t1;

    // bq = wb^T q, bk = wb^T k
    float r8[8] = {wbr[0]*qv, wbr[1]*qv, wbr[2]*qv, wbr[3]*qv,
                   wbr[0]*kv, wbr[1]*kv, wbr[2]*kv, wbr[3]*kv};
    reduce64<8, false>(r8, red, warp, lane);

    // Rank-1 delta-rule updates (packed)
    float cy = beta0 * (syq - syk);
    float cq = beta1 * (sqq - sqk);
    float ck = beta2 * (skq - skk);
    u64 cy2 = pack2(cy, cy);
    u64 cq2 = pack2(cq, cq);
    u64 ck2 = pack2(ck, ck);
    #pragma unroll
    for (int d = 0; d < DH/2; d++) {
      u64 kd = k2[d];
      wy2[d] = fma2(cy2, kd, wy2[d]);
      wq2[d] = fma2(cq2, kd, wq2[d]);
      wk2[d] = fma2(ck2, kd, wk2[d]);
    }
    float bko = beta3 * kv;
    #pragma unroll
    for (int j = 0; j < 4; j++)
      wbr[j] = fmaf(bko, r8[j] - r8[4 + j], wbr[j]);

    // out_t = softmax(y) -> bf16 for the tensor-core GEMM
    yout[(size_t)t * (BSZ * INDIM) + tid] = __float2bfloat16(outv);
  }
}

// ---------------------------------------------------------------------------
// LayerNorm row statistics for h (32768 rows of 1024)
// ---------------------------------------------------------------------------
__global__ void __launch_bounds__(256) ln_stats_kernel(const float* __restrict__ hin)
{
  const int row  = blockIdx.x;
  const int tid  = threadIdx.x;
  const int lane = tid & 31;
  const int warp = tid >> 5;

  float4 v = *(const float4*)(hin + (size_t)row * INDIM + tid * 4);
  float s  = v.x + v.y + v.z + v.w;
  float s2 = v.x * v.x + v.y * v.y + v.z * v.z + v.w * v.w;

  #pragma unroll
  for (int off = 16; off > 0; off >>= 1) {
    s  += __shfl_xor_sync(0xffffffffu, s, off);
    s2 += __shfl_xor_sync(0xffffffffu, s2, off);
  }
  __shared__ float sa[8], sb[8];
  if (lane == 0) { sa[warp] = s; sb[warp] = s2; }
  __syncthreads();
  if (tid == 0) {
    float S = 0.f, S2 = 0.f;
    #pragma unroll
    for (int i = 0; i < 8; i++) { S += sa[i]; S2 += sb[i]; }
    float m   = S * (1.f / INDIM);
    float var = S2 * (1.f / INDIM) - m * m;
    g_mu[row]   = m;
    g_rstd[row] = rsqrtf(var + 1e-5f);
  }
}

// ---------------------------------------------------------------------------
// out_w fp32 -> bf16
// ---------------------------------------------------------------------------
__global__ void __launch_bounds__(256) convert_w_kernel(const float* __restrict__ w)
{
  int i = blockIdx.x * 256 + threadIdx.x;       // each handles 4 elems
  float4 v = ((const float4*)w)[i];
  __nv_bfloat162* o = (__nv_bfloat162*)g_wb16;
  o[2*i]   = __nv_bfloat162(__float2bfloat16(v.x), __float2bfloat16(v.y));
  o[2*i+1] = __nv_bfloat162(__float2bfloat16(v.z), __float2bfloat16(v.w));
}

// ---------------------------------------------------------------------------
// bf16 tensor-core GEMM helpers (plain functions only — no macros/lambdas)
// ---------------------------------------------------------------------------
__device__ __forceinline__ void cp_async16(unsigned int saddr, const void* gptr) {
  asm volatile("cp.async.cg.shared.global [%0], [%1], 16;\n" :: "r"(saddr), "l"(gptr));
}
__device__ __forceinline__ void cp_commit() {
  asm volatile("cp.async.commit_group;\n");
}
__device__ __forceinline__ void cp_wait1() {
  asm volatile("cp.async.wait_group 1;\n");
}
__device__ __forceinline__ void cp_wait0() {
  asm volatile("cp.async.wait_group 0;\n");
}
__device__ __forceinline__ void ldsm4(unsigned int& r0, unsigned int& r1,
                                      unsigned int& r2, unsigned int& r3,
                                      unsigned int addr) {
  asm volatile("ldmatrix.sync.aligned.m8n8.x4.shared.b16 {%0,%1,%2,%3}, [%4];"
               : "=r"(r0), "=r"(r1), "=r"(r2), "=r"(r3) : "r"(addr));
}
__device__ __forceinline__ void mma_bf16(float* c, unsigned int a0, unsigned int a1,
                                         unsigned int a2, unsigned int a3,
                                         unsigned int b0, unsigned int b1) {
  asm volatile(
    "mma.sync.aligned.m16n8k16.row.col.f32.bf16.bf16.f32 "
    "{%0,%1,%2,%3}, {%4,%5,%6,%7}, {%8,%9}, {%0,%1,%2,%3};"
    : "+f"(c[0]), "+f"(c[1]), "+f"(c[2]), "+f"(c[3])
    : "r"(a0), "r"(a1), "r"(a2), "r"(a3), "r"(b0), "r"(b1));
}

#define GBM 128
#define GBN 128
#define GBK 32
#define TSTRIDE 40   // bf16 elems per smem row: 80B stride, conflict-free

// Loads one 128x32 bf16 tile of A and B into the given smem buffers.
// 256 threads, 2 chunks each per operand; chunk = 16B = 8 bf16.
__device__ __forceinline__ void load_tile_fn(
    unsigned int sAbuf, unsigned int sBbuf,
    const __nv_bfloat16* Aptr, const __nv_bfloat16* Bptr,
    int m0, int n0, int k0, int tid)
{
  #pragma unroll
  for (int i = 0; i < 2; i++) {
    int c   = tid + i * 256;
    int row = c >> 2;
    int seg = c & 3;
    unsigned int soff = (unsigned int)(row * TSTRIDE + seg * 8) * 2;
    cp_async16(sAbuf + soff, Aptr + (size_t)(m0 + row) * INDIM + k0 + seg * 8);
    cp_async16(sBbuf + soff, Bptr + (size_t)(n0 + row) * INDIM + k0 + seg * 8);
  }
}

__global__ void __launch_bounds__(256, 2) gemm_bf16_ln(
    const float* __restrict__ hin,
    const float* __restrict__ gvec,
    const float* __restrict__ bvec,
    float* __restrict__ out)
{
  __shared__ __nv_bfloat16 As[2][GBM * TSTRIDE];
  __shared__ __nv_bfloat16 Bs[2][GBN * TSTRIDE];

  const int m0  = blockIdx.y * GBM;
  const int n0  = blockIdx.x * GBN;
  const int tid = threadIdx.x;
  const int lane = tid & 31;
  const int warp = tid >> 5;
  const int wm = warp >> 2;       // 0..1
  const int wn = warp & 3;        // 0..3

  const __nv_bfloat16* Abf = g_ys_bf;
  const __nv_bfloat16* Bbf = g_wb16;

  unsigned int sA0 = (unsigned int)__cvta_generic_to_shared(&As[0][0]);
  unsigned int sA1 = (unsigned int)__cvta_generic_to_shared(&As[1][0]);
  unsigned int sB0 = (unsigned int)__cvta_generic_to_shared(&Bs[0][0]);
  unsigned int sB1 = (unsigned int)__cvta_generic_to_shared(&Bs[1][0]);

  float acc[4][4][4];
  #pragma unroll
  for (int i = 0; i < 4; i++)
    #pragma unroll
    for (int j = 0; j < 4; j++)
      #pragma unroll
      for (int r = 0; r < 4; r++) acc[i][j][r] = 0.f;

  load_tile_fn(sA0, sB0, Abf, Bbf, m0, n0, 0, tid);
  cp_commit();

  const int NKT = INDIM / GBK;   // 32
  for (int kt = 0; kt < NKT; kt++) {
    if (kt + 1 < NKT) {
      unsigned int sAn = ((kt + 1) & 1) ? sA1 : sA0;
      unsigned int sBn = ((kt + 1) & 1) ? sB1 : sB0;
      load_tile_fn(sAn, sBn, Abf, Bbf, m0, n0, (kt + 1) * GBK, tid);
      cp_commit();
      cp_wait1();
    } else {
      cp_wait0();
    }
    __syncthreads();

    unsigned int sAc = (kt & 1) ? sA1 : sA0;
    unsigned int sBc = (kt & 1) ? sB1 : sB0;

    #pragma unroll
    for (int ks = 0; ks < 2; ks++) {
      int koff = ks * 16;
      unsigned int a[4][4];
      #pragma unroll
      for (int mt = 0; mt < 4; mt++) {
        int row = wm * 64 + mt * 16 + (lane & 15);
        int col = koff + 8 * (lane >> 4);
        ldsm4(a[mt][0], a[mt][1], a[mt][2], a[mt][3],
              sAc + (unsigned int)(row * TSTRIDE + col) * 2);
      }
      unsigned int bfrag[4][2];
      #pragma unroll
      for (int half = 0; half < 2; half++) {
        int row = wn * 32 + half * 16 + (lane & 15);
        int col = koff + 8 * (lane >> 4);
        unsigned int r0, r1, r2, r3;
        ldsm4(r0, r1, r2, r3, sBc + (unsigned int)(row * TSTRIDE + col) * 2);
        bfrag[half*2+0][0] = r0; bfrag[half*2+0][1] = r2;
        bfrag[half*2+1][0] = r1; bfrag[half*2+1][1] = r3;
      }
      #pragma unroll
      for (int mt = 0; mt < 4; mt++)
        #pragma unroll
        for (int nt = 0; nt < 4; nt++)
          mma_bf16(acc[mt][nt], a[mt][0], a[mt][1], a[mt][2], a[mt][3],
                   bfrag[nt][0], bfrag[nt][1]);
    }
    __syncthreads();
  }

  // Epilogue: add LN(h) residual
  #pragma unroll
  for (int mt = 0; mt < 4; mt++) {
    int mbase = m0 + wm * 64 + mt * 16 + (lane >> 2);
    #pragma unroll
    for (int rr = 0; rr < 2; rr++) {
      int m = mbase + rr * 8;
      float muv = g_mu[m];
      float rs  = g_rstd[m];
      #pragma unroll
      for (int nt = 0; nt < 4; nt++) {
        int n = n0 + wn * 32 + nt * 8 + 2 * (lane & 3);
        float2 hv = *(const float2*)(hin + (size_t)m * INDIM + n);
        float2 gv = *(const float2*)(gvec + n);
        float2 bv = *(const float2*)(bvec + n);
        float2 o;
        o.x = acc[mt][nt][rr*2+0] + (hv.x - muv) * rs * gv.x + bv.x;
        o.y = acc[mt][nt][rr*2+1] + (hv.y - muv) * rs * gv.y + bv.y;
        *(float2*)(out + (size_t)m * INDIM + n) = o;
      }
    }
  }
}

// ---------------------------------------------------------------------------
extern "C" void kernel_launch(void* const* d_in, const int* in_sizes, int n_in,
                              void* d_out, int out_size)
{
  const float* h_in = (const float*)d_in[0];
  const float* W_y  = (const float*)d_in[1];
  const float* W_q  = (const float*)d_in[2];
  const float* W_k  = (const float*)d_in[3];
  const float* w_b  = (const float*)d_in[4];
  const float* outw = (const float*)d_in[5];
  const float* ln_g = (const float*)d_in[6];
  const float* ln_b = (const float*)d_in[7];
  float* out = (float*)d_out;

  // Small independent prep
  convert_w_kernel<<<INDIM * INDIM / 4 / 256, 256>>>(outw);
  ln_stats_kernel<<<MROWS, 256>>>(h_in);

  // Sequential SRWM scan: 512 units, 64 threads each (packed f32x2)
  srwm_scan<<<BSZ * NH, 64>>>(h_in, W_y, W_q, W_k, w_b);

  // Output GEMM (bf16 tensor cores) + LN residual
  dim3 grid(INDIM / GBN, MROWS / GBM);
  gemm_bf16_ln<<<grid, 256>>>(h_in, ln_g, ln_b, out);
}